// round 4
// baseline (speedup 1.0000x reference)
#include <cuda_runtime.h>
#include <math.h>

#define Bb  8
#define Cc  64
#define Hh  128
#define Ww  128
#define HW  (Hh*Ww)
#define K2  9
#define OCT 27          // 18 offset + 9 mask channels
#define CK  (Cc*K2)     // 576
#define PIX 16          // pixels per group
#define SROW 577        // padded samp row (bank-conflict-free broadcast)
#define GPB 8           // pixel-groups per block
#define NGROUPS ((Bb*HW)/PIX)   // 8192
#define DEF_BLOCKS (NGROUPS/GPB) // 1024

// scratch (static __device__ — allocation-free per harness rules)
__device__ float g_dy[Bb*HW*K2];
__device__ float g_dx[Bb*HW*K2];
__device__ float g_mk[Bb*HW*K2];
__device__ float g_wT[CK*Cc];   // dw transposed to [j=c*9+k][o]

// ---------------------------------------------------------------------------
// dw [O=64][C=64][3][3] -> wT [576][64]
__global__ void transpose_w_kernel(const float* __restrict__ dw) {
    int i = blockIdx.x * 256 + threadIdx.x;
    if (i < Cc * CK) {
        int o = i / CK;
        int j = i - o * CK;
        g_wT[j * Cc + o] = dw[i];
    }
}

// ---------------------------------------------------------------------------
// Offset + mask conv (3x3, SAME). grid (H, B), block 128 (= W).
// Produces dy/dx (with bias) and sigmoid(mask) per (b,h,w,k).
__global__ __launch_bounds__(128)
void offmask_kernel(const float* __restrict__ x,
                    const float* __restrict__ ow, const float* __restrict__ ob,
                    const float* __restrict__ mw, const float* __restrict__ mb)
{
    extern __shared__ float wsh[];  // [27][576] = 62208 B
    const int h = blockIdx.x;
    const int b = blockIdx.y;
    const int w = threadIdx.x;

    for (int i = threadIdx.x; i < 18 * CK; i += 128) wsh[i] = ow[i];
    for (int i = threadIdx.x; i < 9  * CK; i += 128) wsh[18 * CK + i] = mw[i];
    __syncthreads();

    float acc[OCT];
#pragma unroll
    for (int oc = 0; oc < OCT; oc++) acc[oc] = 0.f;

    const float* xb = x + (size_t)b * Cc * HW;
    for (int c = 0; c < Cc; c++) {
        const float* xc = xb + c * HW;
        float xv[9];
#pragma unroll
        for (int ky = 0; ky < 3; ky++) {
            int hh = h + ky - 1;
            bool hv = (unsigned)hh < (unsigned)Hh;
#pragma unroll
            for (int kx = 0; kx < 3; kx++) {
                int ww = w + kx - 1;
                bool wv = (unsigned)ww < (unsigned)Ww;
                xv[ky * 3 + kx] = (hv && wv) ? xc[hh * Ww + ww] : 0.f;
            }
        }
        const float* wc = wsh + c * 9;
#pragma unroll
        for (int k = 0; k < 9; k++) {
            float xk = xv[k];
#pragma unroll
            for (int oc = 0; oc < OCT; oc++)
                acc[oc] = fmaf(xk, wc[oc * CK + k], acc[oc]);
        }
    }

    const int P = (b * Hh + h) * Ww + w;
#pragma unroll
    for (int k = 0; k < 9; k++) {
        g_dy[P * 9 + k] = acc[2 * k]     + ob[2 * k];
        g_dx[P * 9 + k] = acc[2 * k + 1] + ob[2 * k + 1];
        float z = acc[18 + k] + mb[k];
        g_mk[P * 9 + k] = 1.f / (1.f + expf(-z));
    }
}

// ---------------------------------------------------------------------------
// Deformable conv: per block, weight matrix in smem; loop over pixel-groups.
// Stage 1: modulated bilinear samples -> smem. Stage 2: 64x576 GEMV x 16 px.
__global__ __launch_bounds__(256, 1)
void deform_kernel(const float* __restrict__ x,
                   const float* __restrict__ db,
                   float* __restrict__ out)
{
    extern __shared__ float sm[];
    float* wsh  = sm;                    // 576*64
    float* samp = sm + CK * Cc;          // 16*577
    float* sdy  = samp + PIX * SROW;     // 16*9
    float* sdx  = sdy + PIX * K2;
    float* smk  = sdx + PIX * K2;

    const int tid = threadIdx.x;
    for (int i = tid; i < CK * Cc; i += 256) wsh[i] = g_wT[i];
    __syncthreads();

    const int g_end = blockIdx.x * GPB + GPB;
    for (int g = blockIdx.x * GPB; g < g_end; g++) {
        const int P0  = g * PIX;
        const int b   = P0 / HW;
        const int hw0 = P0 - b * HW;

        for (int i = tid; i < PIX * K2; i += 256) {
            sdy[i] = g_dy[P0 * 9 + i];
            sdx[i] = g_dx[P0 * 9 + i];
            smk[i] = g_mk[P0 * 9 + i];
        }
        __syncthreads();

        // ---- stage 1: bilinear sample (lanes span pixels -> coalesced) ----
        {
            const int p  = tid & 15;
            const int hw = hw0 + p;
            const int h  = hw >> 7;
            const int w  = hw & 127;
            const float* xb = x + (size_t)b * Cc * HW;
            for (int j = tid >> 4; j < CK; j += 16) {
                const int c = j / 9;
                const int k = j - c * 9;
                const float dy = sdy[p * 9 + k];
                const float dx = sdx[p * 9 + k];
                const float mv = smk[p * 9 + k];
                const float py = (float)(h + k / 3 - 1) + dy;
                const float px = (float)(w + k % 3 - 1) + dx;
                const float y0f = floorf(py), x0f = floorf(px);
                const int y0 = (int)y0f, x0 = (int)x0f;
                const float ly = py - y0f, lx = px - x0f;
                const bool y0v = (unsigned)y0       < (unsigned)Hh;
                const bool y1v = (unsigned)(y0 + 1) < (unsigned)Hh;
                const bool x0v = (unsigned)x0       < (unsigned)Ww;
                const bool x1v = (unsigned)(x0 + 1) < (unsigned)Ww;
                const float* xc = xb + c * HW;
                const float* r0 = xc + y0 * Ww;
                const float* r1 = r0 + Ww;
                float v00 = (y0v && x0v) ? r0[x0]     : 0.f;
                float v01 = (y0v && x1v) ? r0[x0 + 1] : 0.f;
                float v10 = (y1v && x0v) ? r1[x0]     : 0.f;
                float v11 = (y1v && x1v) ? r1[x0 + 1] : 0.f;
                float v = (1.f - ly) * ((1.f - lx) * v00 + lx * v01)
                        +        ly  * ((1.f - lx) * v10 + lx * v11);
                samp[p * SROW + j] = v * mv;
            }
        }
        __syncthreads();

        // ---- stage 2: out[16px][64o] = samp[16][576] @ wT[576][64] ----
        {
            const int og = tid & 15;       // float4 output group
            const int p  = tid >> 4;
            const float4* w4 = (const float4*)wsh;
            const float*  sp = samp + p * SROW;
            float4 acc = make_float4(0.f, 0.f, 0.f, 0.f);
#pragma unroll 8
            for (int j = 0; j < CK; j++) {
                const float  s  = sp[j];
                const float4 wv = w4[j * 16 + og];
                acc.x = fmaf(s, wv.x, acc.x);
                acc.y = fmaf(s, wv.y, acc.y);
                acc.z = fmaf(s, wv.z, acc.z);
                acc.w = fmaf(s, wv.w, acc.w);
            }
            const int hw = hw0 + p;
            const int o  = og * 4;
            float* op = out + (size_t)b * Cc * HW + hw;
            op[(size_t)(o + 0) * HW] = acc.x + db[o + 0];
            op[(size_t)(o + 1) * HW] = acc.y + db[o + 1];
            op[(size_t)(o + 2) * HW] = acc.z + db[o + 2];
            op[(size_t)(o + 3) * HW] = acc.w + db[o + 3];
        }
        __syncthreads();
    }
}

// ---------------------------------------------------------------------------
extern "C" void kernel_launch(void* const* d_in, const int* in_sizes, int n_in,
                              void* d_out, int out_size)
{
    const float* x  = (const float*)d_in[0];
    const float* ow = (const float*)d_in[1];
    const float* ob = (const float*)d_in[2];
    const float* mw = (const float*)d_in[3];
    const float* mb = (const float*)d_in[4];
    const float* dw = (const float*)d_in[5];
    const float* db = (const float*)d_in[6];
    float* out = (float*)d_out;

    const int SMEM1 = OCT * CK * (int)sizeof(float);                       // 62208
    const int SMEM2 = (CK * Cc + PIX * SROW + 3 * PIX * K2) * (int)sizeof(float); // 186112

    cudaFuncSetAttribute(offmask_kernel,
                         cudaFuncAttributeMaxDynamicSharedMemorySize, SMEM1);
    cudaFuncSetAttribute(deform_kernel,
                         cudaFuncAttributeMaxDynamicSharedMemorySize, SMEM2);

    transpose_w_kernel<<<(Cc * CK + 255) / 256, 256>>>(dw);
    offmask_kernel<<<dim3(Hh, Bb), 128, SMEM1>>>(x, ow, ob, mw, mb);
    deform_kernel<<<DEF_BLOCKS, 256, SMEM2>>>(x, db, out);
}

// round 8
// speedup vs baseline: 5.2739x; 5.2739x over previous
#include <cuda_runtime.h>
#include <cuda_bf16.h>
#include <cstdint>
#include <math.h>

#define Bb  8
#define Cc  64
#define Hh  128
#define Ww  128
#define HW  (Hh*Ww)
#define K2  9
#define OCT 27
#define CK  (Cc*K2)     // 576

// ---------------------------------------------------------------------------
// helpers
// ---------------------------------------------------------------------------
__device__ __forceinline__ uint32_t smem_to_u32(const void* p) {
    uint32_t a;
    asm("{ .reg .u64 t; cvta.to.shared.u64 t, %1; cvt.u32.u64 %0, t; }"
        : "=r"(a) : "l"(p));
    return a;
}
#define LDSM_X4(r, ad) \
    asm volatile("ldmatrix.sync.aligned.m8n8.x4.shared.b16 {%0,%1,%2,%3}, [%4];" \
        : "=r"((r)[0]), "=r"((r)[1]), "=r"((r)[2]), "=r"((r)[3]) : "r"(ad))
#define LDSM_X4T(r, ad) \
    asm volatile("ldmatrix.sync.aligned.m8n8.x4.trans.shared.b16 {%0,%1,%2,%3}, [%4];" \
        : "=r"((r)[0]), "=r"((r)[1]), "=r"((r)[2]), "=r"((r)[3]) : "r"(ad))
#define STS128(ad, r0, r1, r2, r3) \
    asm volatile("st.shared.v4.b32 [%0], {%1,%2,%3,%4};" \
        :: "r"(ad), "r"(r0), "r"(r1), "r"(r2), "r"(r3) : "memory")
#define MMA_BF16(d, a, b0, b1) \
    asm volatile("mma.sync.aligned.m16n8k16.row.col.f32.bf16.bf16.f32 " \
        "{%0,%1,%2,%3}, {%4,%5,%6,%7}, {%8,%9}, {%0,%1,%2,%3};" \
        : "+f"((d)[0]), "+f"((d)[1]), "+f"((d)[2]), "+f"((d)[3]) \
        : "r"((a)[0]), "r"((a)[1]), "r"((a)[2]), "r"((a)[3]), "r"(b0), "r"(b1))

// ---------------------------------------------------------------------------
// scratch (static __device__ — allocation-free)
__device__ float g_dy[Bb*HW*K2];
__device__ float g_dx[Bb*HW*K2];
__device__ float g_mk[Bb*HW*K2];
// pre-swizzled bf16 B tiles: [9 chunks][64 k-rows(c) x 64 cols(o)], 128B rows,
// SW128 XOR swizzle; hi and lo halves of the bf16 split.
__device__ uint4 g_Bh4[9*8192/16];
__device__ uint4 g_Bl4[9*8192/16];

// ---------------------------------------------------------------------------
// Weight prep: dw[o][c][k] -> B[k-chunk][row=c][col=o], bf16 hi/lo, swizzled.
__global__ void prep_b_kernel(const float* __restrict__ dw) {
    int i = blockIdx.x * 256 + threadIdx.x;
    if (i >= Cc * CK) return;
    int o = i / CK;
    int r = i - o * CK;
    int c = r / 9;
    int k = r - c * 9;
    float v = dw[i];
    __nv_bfloat16 hi = __float2bfloat16(v);
    __nv_bfloat16 lo = __float2bfloat16(v - __bfloat162float(hi));
    uint32_t off = (uint32_t)c * 128u + (uint32_t)o * 2u;
    uint32_t sw  = off ^ ((off >> 3) & 0x70u);
    ((__nv_bfloat16*)g_Bh4)[k * 4096 + (sw >> 1)] = hi;
    ((__nv_bfloat16*)g_Bl4)[k * 4096 + (sw >> 1)] = lo;
}

// ---------------------------------------------------------------------------
// Offset + mask conv (3x3, SAME). TM=4 rows per thread. grid (H/4, B), 128 thr.
__global__ __launch_bounds__(128)
void offmask_kernel(const float* __restrict__ x,
                    const float* __restrict__ ow, const float* __restrict__ ob,
                    const float* __restrict__ mw, const float* __restrict__ mb)
{
    extern __shared__ float wsh[];  // [27][576]
    const int h0 = blockIdx.x * 4;
    const int b  = blockIdx.y;
    const int w  = threadIdx.x;

    for (int i = threadIdx.x; i < 18 * CK; i += 128) wsh[i] = ow[i];
    for (int i = threadIdx.x; i < 9  * CK; i += 128) wsh[18 * CK + i] = mw[i];
    __syncthreads();

    float acc[4 * OCT];
#pragma unroll
    for (int i = 0; i < 4 * OCT; i++) acc[i] = 0.f;

    const float* xb = x + (size_t)b * Cc * HW;
    for (int c = 0; c < Cc; c++) {
        const float* xc = xb + c * HW;
        float r[18];
#pragma unroll
        for (int ry = 0; ry < 6; ry++) {
            int hh = h0 - 1 + ry;
            bool hv = (unsigned)hh < (unsigned)Hh;
            const float* row = xc + hh * Ww;
#pragma unroll
            for (int rx = 0; rx < 3; rx++) {
                int ww = w - 1 + rx;
                r[ry * 3 + rx] = (hv && (unsigned)ww < (unsigned)Ww) ? row[ww] : 0.f;
            }
        }
        const float* wc = wsh + c * 9;
#pragma unroll
        for (int k = 0; k < 9; k++) {
            const int ky = k / 3, kx = k % 3;
#pragma unroll
            for (int oc = 0; oc < OCT; oc++) {
                float wk = wc[oc * CK + k];
#pragma unroll
                for (int t = 0; t < 4; t++)
                    acc[t * OCT + oc] = fmaf(r[(t + ky) * 3 + kx], wk, acc[t * OCT + oc]);
            }
        }
    }

#pragma unroll
    for (int t = 0; t < 4; t++) {
        const int P = ((b * Hh + h0 + t) * Ww + w);
#pragma unroll
        for (int k = 0; k < 9; k++) {
            g_dy[P * 9 + k] = acc[t * OCT + 2 * k]     + ob[2 * k];
            g_dx[P * 9 + k] = acc[t * OCT + 2 * k + 1] + ob[2 * k + 1];
            float z = acc[t * OCT + 18 + k] + mb[k];
            g_mk[P * 9 + k] = 1.f / (1.f + expf(-z));
        }
    }
}

// ---------------------------------------------------------------------------
// Deformable conv via mma.sync bf16 (3-product hi/lo split), K permuted
// k-major (chunk ch = tap k, 64 channels per chunk).
// CTA = 128 pixels (M=128), 256 threads (8 warps). Sampling: thread t handles
// pixel t&127, channel half t>>7 (32 ch). A staged in smem (SW128 swizzled
// 128B rows), read with ldmatrix.x4. B pre-swizzled in smem, ldmatrix.x4.trans.
// Per warp: M-tile 16 rows, full N=64; acc[8 ntiles][4] fp32 across 9 chunks.
#define SM_A_HI 147456
#define SM_A_LO (147456 + 16384)
#define SMEM2   (147456 + 32768)

__global__ __launch_bounds__(256, 1)
void deform_kernel(const float* __restrict__ x,
                   const float* __restrict__ db,
                   float* __restrict__ out)
{
    extern __shared__ char smd[];
    const uint32_t smem_base = smem_to_u32(smd);
    const int tid = threadIdx.x;

    // load pre-swizzled B tiles: hi at [0,73728), lo at [73728,147456)
    {
        float4* b4 = (float4*)smd;
        for (int i = tid; i < 4608; i += 256) b4[i] = ((const float4*)g_Bh4)[i];
        for (int i = tid; i < 4608; i += 256) b4[4608 + i] = ((const float4*)g_Bl4)[i];
    }

    // ---- sampling-role mapping ----
    const int set = tid >> 7;        // channel half
    const int p   = tid & 127;       // pixel row within CTA
    const int pixel = blockIdx.x * 128 + p;
    const int b  = pixel >> 14;
    const int hw = pixel & (HW - 1);
    const int h  = hw >> 7;
    const int w  = hw & 127;
    const float* xb = x + (size_t)b * Cc * HW + (size_t)(set * 32) * HW;
    const int p9 = pixel * 9;
    const uint32_t a_row_byte = (uint32_t)p * 128u;
    const uint32_t a_row_sw   = ((uint32_t)(p & 7)) << 4;

    // ---- MMA-role mapping ----
    const int wid  = tid >> 5;
    const int lane = tid & 31;
    const int m0   = wid * 16;
    const uint32_t lm_arow = (uint32_t)(m0 + (lane & 15));
    const uint32_t lm_asub = ((uint32_t)(lane >> 4) & 1u) * 16u;
    const uint32_t lm_asw  = (lm_arow & 7u) << 4;
    const uint32_t lm_abase = lm_arow * 128u;
    const uint32_t lm_bkrow = (uint32_t)(lane & 15);
    const uint32_t lm_bnsub = ((uint32_t)(lane >> 4) & 1u) * 16u;

    float acc[8][4];
#pragma unroll
    for (int n = 0; n < 8; n++)
#pragma unroll
        for (int q = 0; q < 4; q++) acc[n][q] = 0.f;

    for (int ch = 0; ch < 9; ch++) {
        // ---- per-tap precompute (k = ch fixed for whole chunk) ----
        const int k = ch;
        const float m  = g_mk[p9 + k];
        const float py = (float)(h + k / 3 - 1) + g_dy[p9 + k];
        const float px = (float)(w + k % 3 - 1) + g_dx[p9 + k];
        const float yf = floorf(py), xf = floorf(px);
        const int   y0 = (int)yf,  x0 = (int)xf;
        const float ly = py - yf,  lx = px - xf;
        const bool y0v = (unsigned)y0       < (unsigned)Hh;
        const bool y1v = (unsigned)(y0 + 1) < (unsigned)Hh;
        const bool x0v = (unsigned)x0       < (unsigned)Ww;
        const bool x1v = (unsigned)(x0 + 1) < (unsigned)Ww;
        const float w00 = (y0v && x0v) ? (1.f - ly) * (1.f - lx) * m : 0.f;
        const float w01 = (y0v && x1v) ? (1.f - ly) * lx         * m : 0.f;
        const float w10 = (y1v && x0v) ? ly         * (1.f - lx) * m : 0.f;
        const float w11 = (y1v && x1v) ? ly         * lx         * m : 0.f;
        const int cy0 = min(max(y0, 0), Hh - 1), cy1 = min(max(y0 + 1, 0), Hh - 1);
        const int cx0 = min(max(x0, 0), Ww - 1), cx1 = min(max(x0 + 1, 0), Ww - 1);
        const int i00 = cy0 * Ww + cx0, i01 = cy0 * Ww + cx1;
        const int i10 = cy1 * Ww + cx0, i11 = cy1 * Ww + cx1;

        // ---- sample 32 channels, split to bf16 hi/lo (pairs packed) ----
        uint32_t hi16[16], lo16[16];
        {
            const float* xc = xb;
#pragma unroll
            for (int i = 0; i < 16; i++) {
                float s0 = w00 * xc[i00] + w01 * xc[i01] + w10 * xc[i10] + w11 * xc[i11];
                xc += HW;
                float s1 = w00 * xc[i00] + w01 * xc[i01] + w10 * xc[i10] + w11 * xc[i11];
                xc += HW;
                __nv_bfloat16 h0b = __float2bfloat16(s0);
                __nv_bfloat16 h1b = __float2bfloat16(s1);
                __nv_bfloat162 hp = __nv_bfloat162(h0b, h1b);
                __nv_bfloat162 lp = __floats2bfloat162_rn(s0 - __bfloat162float(h0b),
                                                          s1 - __bfloat162float(h1b));
                hi16[i] = *(uint32_t*)&hp;
                lo16[i] = *(uint32_t*)&lp;
            }
        }

        __syncthreads();   // all warps done reading A (prev chunk) / B stores visible (ch 0)

        // ---- stage A hi/lo (4 x 16B each, swizzled) ----
#pragma unroll
        for (int u = 0; u < 4; u++) {
            uint32_t col = (((uint32_t)set * 64u) + (uint32_t)u * 16u) ^ a_row_sw;
            uint32_t adh = smem_base + SM_A_HI + a_row_byte + col;
            uint32_t adl = smem_base + SM_A_LO + a_row_byte + col;
            STS128(adh, hi16[u*4+0], hi16[u*4+1], hi16[u*4+2], hi16[u*4+3]);
            STS128(adl, lo16[u*4+0], lo16[u*4+1], lo16[u*4+2], lo16[u*4+3]);
        }
        __syncthreads();

        // ---- MMA: 4 k-steps x 8 n-tiles x 3 split products ----
        const uint32_t bh_base = smem_base + (uint32_t)ch * 8192u;
        const uint32_t bl_base = smem_base + 73728u + (uint32_t)ch * 8192u;
#pragma unroll
        for (int ks = 0; ks < 4; ks++) {
            uint32_t kcol = (((uint32_t)ks * 32u) + lm_asub) ^ lm_asw;
            uint32_t ah[4], al[4];
            LDSM_X4(ah, smem_base + SM_A_HI + lm_abase + kcol);
            LDSM_X4(al, smem_base + SM_A_LO + lm_abase + kcol);
            const uint32_t brow = (uint32_t)ks * 16u + lm_bkrow;
            const uint32_t bsw  = (brow & 7u) << 4;
            const uint32_t boff = brow * 128u;
#pragma unroll
            for (int nt2 = 0; nt2 < 4; nt2++) {
                uint32_t ncol = (((uint32_t)nt2 * 32u) + lm_bnsub) ^ bsw;
                uint32_t bh[4], bl[4];
                LDSM_X4T(bh, bh_base + boff + ncol);
                LDSM_X4T(bl, bl_base + boff + ncol);
                MMA_BF16(acc[2*nt2],     ah, bh[0], bh[1]);
                MMA_BF16(acc[2*nt2],     ah, bl[0], bl[1]);
                MMA_BF16(acc[2*nt2],     al, bh[0], bh[1]);
                MMA_BF16(acc[2*nt2 + 1], ah, bh[2], bh[3]);
                MMA_BF16(acc[2*nt2 + 1], ah, bl[2], bl[3]);
                MMA_BF16(acc[2*nt2 + 1], al, bh[2], bh[3]);
            }
        }
    }

    // ---- epilogue: acc fragment -> out[b][o][hw] (+bias) ----
    const int pix0 = blockIdx.x * 128;          // CTA never straddles b
    const int bB   = pix0 >> 14;
    const int hw0  = (pix0 & (HW - 1)) + m0 + (lane >> 2);
    float* ob = out + (size_t)bB * Cc * HW;
#pragma unroll
    for (int nt = 0; nt < 8; nt++) {
        const int ch0 = nt * 8 + (lane & 3) * 2;
        const float b0 = db[ch0], b1 = db[ch0 + 1];
        ob[(size_t)ch0       * HW + hw0]     = acc[nt][0] + b0;
        ob[(size_t)(ch0 + 1) * HW + hw0]     = acc[nt][1] + b1;
        ob[(size_t)ch0       * HW + hw0 + 8] = acc[nt][2] + b0;
        ob[(size_t)(ch0 + 1) * HW + hw0 + 8] = acc[nt][3] + b1;
    }
}

// ---------------------------------------------------------------------------
extern "C" void kernel_launch(void* const* d_in, const int* in_sizes, int n_in,
                              void* d_out, int out_size)
{
    const float* x  = (const float*)d_in[0];
    const float* ow = (const float*)d_in[1];
    const float* ob = (const float*)d_in[2];
    const float* mw = (const float*)d_in[3];
    const float* mb = (const float*)d_in[4];
    const float* dw = (const float*)d_in[5];
    const float* db = (const float*)d_in[6];
    float* out = (float*)d_out;

    const int SMEM1 = OCT * CK * (int)sizeof(float);   // 62208

    cudaFuncSetAttribute(offmask_kernel,
                         cudaFuncAttributeMaxDynamicSharedMemorySize, SMEM1);
    cudaFuncSetAttribute(deform_kernel,
                         cudaFuncAttributeMaxDynamicSharedMemorySize, SMEM2);

    prep_b_kernel<<<(Cc * CK + 255) / 256, 256>>>(dw);
    offmask_kernel<<<dim3(Hh / 4, Bb), 128, SMEM1>>>(x, ow, ob, mw, mb);
    deform_kernel<<<(Bb * HW) / 128, 256, SMEM2>>>(x, db, out);
}

// round 9
// speedup vs baseline: 5.8559x; 1.1104x over previous
#include <cuda_runtime.h>
#include <cuda_bf16.h>
#include <cstdint>
#include <math.h>

#define Bb  8
#define Cc  64
#define Hh  128
#define Ww  128
#define HW  (Hh*Ww)
#define K2  9
#define OCT 27
#define CK  (Cc*K2)     // 576

// ---------------------------------------------------------------------------
// helpers
// ---------------------------------------------------------------------------
__device__ __forceinline__ uint32_t smem_to_u32(const void* p) {
    uint32_t a;
    asm("{ .reg .u64 t; cvta.to.shared.u64 t, %1; cvt.u32.u64 %0, t; }"
        : "=r"(a) : "l"(p));
    return a;
}
#define LDSM_X4(r, ad) \
    asm volatile("ldmatrix.sync.aligned.m8n8.x4.shared.b16 {%0,%1,%2,%3}, [%4];" \
        : "=r"((r)[0]), "=r"((r)[1]), "=r"((r)[2]), "=r"((r)[3]) : "r"(ad))
#define LDSM_X4T(r, ad) \
    asm volatile("ldmatrix.sync.aligned.m8n8.x4.trans.shared.b16 {%0,%1,%2,%3}, [%4];" \
        : "=r"((r)[0]), "=r"((r)[1]), "=r"((r)[2]), "=r"((r)[3]) : "r"(ad))
#define STS128(ad, r0, r1, r2, r3) \
    asm volatile("st.shared.v4.b32 [%0], {%1,%2,%3,%4};" \
        :: "r"(ad), "r"(r0), "r"(r1), "r"(r2), "r"(r3) : "memory")
#define MMA_BF16(d, a, b0, b1) \
    asm volatile("mma.sync.aligned.m16n8k16.row.col.f32.bf16.bf16.f32 " \
        "{%0,%1,%2,%3}, {%4,%5,%6,%7}, {%8,%9}, {%0,%1,%2,%3};" \
        : "+f"((d)[0]), "+f"((d)[1]), "+f"((d)[2]), "+f"((d)[3]) \
        : "r"((a)[0]), "r"((a)[1]), "r"((a)[2]), "r"((a)[3]), "r"(b0), "r"(b1))

// ---------------------------------------------------------------------------
// scratch (static __device__ — allocation-free; zero-initialized at load)
__device__ float g_dy[Bb*HW*K2];
__device__ float g_dx[Bb*HW*K2];
__device__ float g_mk[Bb*HW*K2];
// pre-swizzled bf16 B tiles (deform): [9][64 k-rows(c) x 64 cols(o)], 128B rows
__device__ uint4 g_Bh4[9*8192/16];
__device__ uint4 g_Bl4[9*8192/16];
// pre-swizzled bf16 B tiles (offset+mask conv): cols = 27 out-ch padded to 32
__device__ uint4 g_BOh4[9*8192/16];
__device__ uint4 g_BOl4[9*8192/16];

// ---------------------------------------------------------------------------
// Weight prep (deform): dw[o][c][k] -> B[k][row=c][col=o], bf16 hi/lo, swizzled.
__global__ void prep_b_kernel(const float* __restrict__ dw) {
    int i = blockIdx.x * 256 + threadIdx.x;
    if (i >= Cc * CK) return;
    int o = i / CK;
    int r = i - o * CK;
    int c = r / 9;
    int k = r - c * 9;
    float v = dw[i];
    __nv_bfloat16 hi = __float2bfloat16(v);
    __nv_bfloat16 lo = __float2bfloat16(v - __bfloat162float(hi));
    uint32_t off = (uint32_t)c * 128u + (uint32_t)o * 2u;
    uint32_t sw  = off ^ ((off >> 3) & 0x70u);
    ((__nv_bfloat16*)g_Bh4)[k * 4096 + (sw >> 1)] = hi;
    ((__nv_bfloat16*)g_Bl4)[k * 4096 + (sw >> 1)] = lo;
}

// Weight prep (offset+mask): cols j: 0..17 = ow channel j, 18..26 = mw channel
// j-18, 27..31 = zero. Layout B[k][row=c][col=j], 128B rows, SW128 swizzle.
__global__ void prep_bo_kernel(const float* __restrict__ ow,
                               const float* __restrict__ mw) {
    int i = blockIdx.x * 256 + threadIdx.x;          // 9*64*32
    if (i >= 9 * 64 * 32) return;
    int k = i >> 11;
    int c = (i >> 5) & 63;
    int j = i & 31;
    float v = 0.f;
    if (j < 18)      v = ow[j * CK + c * 9 + k];
    else if (j < 27) v = mw[(j - 18) * CK + c * 9 + k];
    __nv_bfloat16 hi = __float2bfloat16(v);
    __nv_bfloat16 lo = __float2bfloat16(v - __bfloat162float(hi));
    uint32_t off = (uint32_t)c * 128u + (uint32_t)j * 2u;
    uint32_t sw  = off ^ ((off >> 3) & 0x70u);
    ((__nv_bfloat16*)g_BOh4)[k * 4096 + (sw >> 1)] = hi;
    ((__nv_bfloat16*)g_BOl4)[k * 4096 + (sw >> 1)] = lo;
}

// ---------------------------------------------------------------------------
// common smem layout for the two MMA kernels
#define SM_A_HI 147456
#define SM_A_LO (147456 + 16384)
#define SMEM2   (147456 + 32768)

// ---------------------------------------------------------------------------
// Offset+mask conv via mma.sync bf16 split. GEMM: M=pixels, K=576 (k-major),
// N=32 (27 used). A chunk = shifted x (tap k), no bilinear. Same staging /
// swizzle / fragment mapping as deform_kernel. Epilogue: bias, sigmoid for
// mask cols, scatter into g_dy/g_dx/g_mk.
__global__ __launch_bounds__(256, 1)
void offmask_mma_kernel(const float* __restrict__ x,
                        const float* __restrict__ obias,
                        const float* __restrict__ mbias)
{
    extern __shared__ char smd[];
    const uint32_t smem_base = smem_to_u32(smd);
    const int tid = threadIdx.x;

    {   // B tiles: hi [0,73728), lo [73728,147456)
        float4* b4 = (float4*)smd;
        for (int i = tid; i < 4608; i += 256) b4[i] = ((const float4*)g_BOh4)[i];
        for (int i = tid; i < 4608; i += 256) b4[4608 + i] = ((const float4*)g_BOl4)[i];
    }

    // sampling-role mapping
    const int set = tid >> 7;
    const int p   = tid & 127;
    const int pixel = blockIdx.x * 128 + p;
    const int b  = pixel >> 14;
    const int hw = pixel & (HW - 1);
    const int h  = hw >> 7;
    const int w  = hw & 127;
    const float* xb = x + (size_t)b * Cc * HW + (size_t)(set * 32) * HW;
    const uint32_t a_row_byte = (uint32_t)p * 128u;
    const uint32_t a_row_sw   = ((uint32_t)(p & 7)) << 4;

    // MMA-role mapping
    const int wid  = tid >> 5;
    const int lane = tid & 31;
    const int m0   = wid * 16;
    const uint32_t lm_arow  = (uint32_t)(m0 + (lane & 15));
    const uint32_t lm_asub  = ((uint32_t)(lane >> 4) & 1u) * 16u;
    const uint32_t lm_asw   = (lm_arow & 7u) << 4;
    const uint32_t lm_abase = lm_arow * 128u;
    const uint32_t lm_bkrow = (uint32_t)(lane & 15);
    const uint32_t lm_bnsub = ((uint32_t)(lane >> 4) & 1u) * 16u;

    float acc[4][4];
#pragma unroll
    for (int n = 0; n < 4; n++)
#pragma unroll
        for (int q = 0; q < 4; q++) acc[n][q] = 0.f;

    for (int ch = 0; ch < 9; ch++) {
        const int hh = h + ch / 3 - 1;
        const int ww = w + ch % 3 - 1;
        const bool ok = ((unsigned)hh < (unsigned)Hh) && ((unsigned)ww < (unsigned)Ww);
        const int ioff = hh * Ww + ww;

        uint32_t hi16[16], lo16[16];
        {
            const float* xc = xb;
#pragma unroll
            for (int i = 0; i < 16; i++) {
                float s0 = ok ? xc[ioff] : 0.f;  xc += HW;
                float s1 = ok ? xc[ioff] : 0.f;  xc += HW;
                __nv_bfloat16 h0b = __float2bfloat16(s0);
                __nv_bfloat16 h1b = __float2bfloat16(s1);
                __nv_bfloat162 hp = __nv_bfloat162(h0b, h1b);
                __nv_bfloat162 lp = __floats2bfloat162_rn(s0 - __bfloat162float(h0b),
                                                          s1 - __bfloat162float(h1b));
                hi16[i] = *(uint32_t*)&hp;
                lo16[i] = *(uint32_t*)&lp;
            }
        }

        __syncthreads();
#pragma unroll
        for (int u = 0; u < 4; u++) {
            uint32_t col = (((uint32_t)set * 64u) + (uint32_t)u * 16u) ^ a_row_sw;
            STS128(smem_base + SM_A_HI + a_row_byte + col,
                   hi16[u*4+0], hi16[u*4+1], hi16[u*4+2], hi16[u*4+3]);
            STS128(smem_base + SM_A_LO + a_row_byte + col,
                   lo16[u*4+0], lo16[u*4+1], lo16[u*4+2], lo16[u*4+3]);
        }
        __syncthreads();

        const uint32_t bh_base = smem_base + (uint32_t)ch * 8192u;
        const uint32_t bl_base = smem_base + 73728u + (uint32_t)ch * 8192u;
#pragma unroll
        for (int ks = 0; ks < 4; ks++) {
            uint32_t kcol = (((uint32_t)ks * 32u) + lm_asub) ^ lm_asw;
            uint32_t ah[4], al[4];
            LDSM_X4(ah, smem_base + SM_A_HI + lm_abase + kcol);
            LDSM_X4(al, smem_base + SM_A_LO + lm_abase + kcol);
            const uint32_t brow = (uint32_t)ks * 16u + lm_bkrow;
            const uint32_t bsw  = (brow & 7u) << 4;
            const uint32_t boff = brow * 128u;
            // N=32 -> single x4T pair covers cols 0..31
            uint32_t ncol = lm_bnsub ^ bsw;
            uint32_t bh[4], bl[4];
            LDSM_X4T(bh, bh_base + boff + ncol);
            LDSM_X4T(bl, bl_base + boff + ncol);
            MMA_BF16(acc[0], ah, bh[0], bh[1]);
            MMA_BF16(acc[0], ah, bl[0], bl[1]);
            MMA_BF16(acc[0], al, bh[0], bh[1]);
            MMA_BF16(acc[1], ah, bh[2], bh[3]);
            MMA_BF16(acc[1], ah, bl[2], bl[3]);
            MMA_BF16(acc[1], al, bh[2], bh[3]);
            uint32_t ncol2 = (32u + lm_bnsub) ^ bsw;
            LDSM_X4T(bh, bh_base + boff + ncol2);
            LDSM_X4T(bl, bl_base + boff + ncol2);
            MMA_BF16(acc[2], ah, bh[0], bh[1]);
            MMA_BF16(acc[2], ah, bl[0], bl[1]);
            MMA_BF16(acc[2], al, bh[0], bh[1]);
            MMA_BF16(acc[3], ah, bh[2], bh[3]);
            MMA_BF16(acc[3], ah, bl[2], bl[3]);
            MMA_BF16(acc[3], al, bh[2], bh[3]);
        }
    }

    // epilogue: col j meaning: j<18 -> offset ch j (even=dy,odd=dx, k=j/2),
    // 18<=j<27 -> mask k=j-18 (sigmoid), j>=27 -> discard.
    const int pix0 = blockIdx.x * 128;
    const int r0 = m0 + (lane >> 2);
#pragma unroll
    for (int nt = 0; nt < 4; nt++) {
        const int j0 = nt * 8 + (lane & 3) * 2;
#pragma unroll
        for (int q = 0; q < 4; q++) {
            const int j = j0 + (q & 1);
            if (j >= 27) continue;
            const int P = pix0 + r0 + ((q >> 1) << 3);
            const float v = acc[nt][q];
            if (j < 18) {
                float t = v + obias[j];
                if ((j & 1) == 0) g_dy[P * 9 + (j >> 1)] = t;
                else              g_dx[P * 9 + (j >> 1)] = t;
            } else {
                float z = v + mbias[j - 18];
                g_mk[P * 9 + (j - 18)] = 1.f / (1.f + expf(-z));
            }
        }
    }
}

// ---------------------------------------------------------------------------
// Deformable conv via mma.sync bf16 split (unchanged from round 8).
__global__ __launch_bounds__(256, 1)
void deform_kernel(const float* __restrict__ x,
                   const float* __restrict__ db,
                   float* __restrict__ out)
{
    extern __shared__ char smd[];
    const uint32_t smem_base = smem_to_u32(smd);
    const int tid = threadIdx.x;

    {
        float4* b4 = (float4*)smd;
        for (int i = tid; i < 4608; i += 256) b4[i] = ((const float4*)g_Bh4)[i];
        for (int i = tid; i < 4608; i += 256) b4[4608 + i] = ((const float4*)g_Bl4)[i];
    }

    const int set = tid >> 7;
    const int p   = tid & 127;
    const int pixel = blockIdx.x * 128 + p;
    const int b  = pixel >> 14;
    const int hw = pixel & (HW - 1);
    const int h  = hw >> 7;
    const int w  = hw & 127;
    const float* xb = x + (size_t)b * Cc * HW + (size_t)(set * 32) * HW;
    const int p9 = pixel * 9;
    const uint32_t a_row_byte = (uint32_t)p * 128u;
    const uint32_t a_row_sw   = ((uint32_t)(p & 7)) << 4;

    const int wid  = tid >> 5;
    const int lane = tid & 31;
    const int m0   = wid * 16;
    const uint32_t lm_arow  = (uint32_t)(m0 + (lane & 15));
    const uint32_t lm_asub  = ((uint32_t)(lane >> 4) & 1u) * 16u;
    const uint32_t lm_asw   = (lm_arow & 7u) << 4;
    const uint32_t lm_abase = lm_arow * 128u;
    const uint32_t lm_bkrow = (uint32_t)(lane & 15);
    const uint32_t lm_bnsub = ((uint32_t)(lane >> 4) & 1u) * 16u;

    float acc[8][4];
#pragma unroll
    for (int n = 0; n < 8; n++)
#pragma unroll
        for (int q = 0; q < 4; q++) acc[n][q] = 0.f;

    for (int ch = 0; ch < 9; ch++) {
        const int k = ch;
        const float m  = g_mk[p9 + k];
        const float py = (float)(h + k / 3 - 1) + g_dy[p9 + k];
        const float px = (float)(w + k % 3 - 1) + g_dx[p9 + k];
        const float yf = floorf(py), xf = floorf(px);
        const int   y0 = (int)yf,  x0 = (int)xf;
        const float ly = py - yf,  lx = px - xf;
        const bool y0v = (unsigned)y0       < (unsigned)Hh;
        const bool y1v = (unsigned)(y0 + 1) < (unsigned)Hh;
        const bool x0v = (unsigned)x0       < (unsigned)Ww;
        const bool x1v = (unsigned)(x0 + 1) < (unsigned)Ww;
        const float w00 = (y0v && x0v) ? (1.f - ly) * (1.f - lx) * m : 0.f;
        const float w01 = (y0v && x1v) ? (1.f - ly) * lx         * m : 0.f;
        const float w10 = (y1v && x0v) ? ly         * (1.f - lx) * m : 0.f;
        const float w11 = (y1v && x1v) ? ly         * lx         * m : 0.f;
        const int cy0 = min(max(y0, 0), Hh - 1), cy1 = min(max(y0 + 1, 0), Hh - 1);
        const int cx0 = min(max(x0, 0), Ww - 1), cx1 = min(max(x0 + 1, 0), Ww - 1);
        const int i00 = cy0 * Ww + cx0, i01 = cy0 * Ww + cx1;
        const int i10 = cy1 * Ww + cx0, i11 = cy1 * Ww + cx1;

        uint32_t hi16[16], lo16[16];
        {
            const float* xc = xb;
#pragma unroll
            for (int i = 0; i < 16; i++) {
                float s0 = w00 * xc[i00] + w01 * xc[i01] + w10 * xc[i10] + w11 * xc[i11];
                xc += HW;
                float s1 = w00 * xc[i00] + w01 * xc[i01] + w10 * xc[i10] + w11 * xc[i11];
                xc += HW;
                __nv_bfloat16 h0b = __float2bfloat16(s0);
                __nv_bfloat16 h1b = __float2bfloat16(s1);
                __nv_bfloat162 hp = __nv_bfloat162(h0b, h1b);
                __nv_bfloat162 lp = __floats2bfloat162_rn(s0 - __bfloat162float(h0b),
                                                          s1 - __bfloat162float(h1b));
                hi16[i] = *(uint32_t*)&hp;
                lo16[i] = *(uint32_t*)&lp;
            }
        }

        __syncthreads();
#pragma unroll
        for (int u = 0; u < 4; u++) {
            uint32_t col = (((uint32_t)set * 64u) + (uint32_t)u * 16u) ^ a_row_sw;
            STS128(smem_base + SM_A_HI + a_row_byte + col,
                   hi16[u*4+0], hi16[u*4+1], hi16[u*4+2], hi16[u*4+3]);
            STS128(smem_base + SM_A_LO + a_row_byte + col,
                   lo16[u*4+0], lo16[u*4+1], lo16[u*4+2], lo16[u*4+3]);
        }
        __syncthreads();

        const uint32_t bh_base = smem_base + (uint32_t)ch * 8192u;
        const uint32_t bl_base = smem_base + 73728u + (uint32_t)ch * 8192u;
#pragma unroll
        for (int ks = 0; ks < 4; ks++) {
            uint32_t kcol = (((uint32_t)ks * 32u) + lm_asub) ^ lm_asw;
            uint32_t ah[4], al[4];
            LDSM_X4(ah, smem_base + SM_A_HI + lm_abase + kcol);
            LDSM_X4(al, smem_base + SM_A_LO + lm_abase + kcol);
            const uint32_t brow = (uint32_t)ks * 16u + lm_bkrow;
            const uint32_t bsw  = (brow & 7u) << 4;
            const uint32_t boff = brow * 128u;
#pragma unroll
            for (int nt2 = 0; nt2 < 4; nt2++) {
                uint32_t ncol = (((uint32_t)nt2 * 32u) + lm_bnsub) ^ bsw;
                uint32_t bh[4], bl[4];
                LDSM_X4T(bh, bh_base + boff + ncol);
                LDSM_X4T(bl, bl_base + boff + ncol);
                MMA_BF16(acc[2*nt2],     ah, bh[0], bh[1]);
                MMA_BF16(acc[2*nt2],     ah, bl[0], bl[1]);
                MMA_BF16(acc[2*nt2],     al, bh[0], bh[1]);
                MMA_BF16(acc[2*nt2 + 1], ah, bh[2], bh[3]);
                MMA_BF16(acc[2*nt2 + 1], ah, bl[2], bl[3]);
                MMA_BF16(acc[2*nt2 + 1], al, bh[2], bh[3]);
            }
        }
    }

    const int pix0 = blockIdx.x * 128;
    const int bB   = pix0 >> 14;
    const int hw0  = (pix0 & (HW - 1)) + m0 + (lane >> 2);
    float* ob = out + (size_t)bB * Cc * HW;
#pragma unroll
    for (int nt = 0; nt < 8; nt++) {
        const int ch0 = nt * 8 + (lane & 3) * 2;
        const float b0 = db[ch0], b1 = db[ch0 + 1];
        ob[(size_t)ch0       * HW + hw0]     = acc[nt][0] + b0;
        ob[(size_t)(ch0 + 1) * HW + hw0]     = acc[nt][1] + b1;
        ob[(size_t)ch0       * HW + hw0 + 8] = acc[nt][2] + b0;
        ob[(size_t)(ch0 + 1) * HW + hw0 + 8] = acc[nt][3] + b1;
    }
}

// ---------------------------------------------------------------------------
extern "C" void kernel_launch(void* const* d_in, const int* in_sizes, int n_in,
                              void* d_out, int out_size)
{
    const float* x  = (const float*)d_in[0];
    const float* ow = (const float*)d_in[1];
    const float* ob = (const float*)d_in[2];
    const float* mw = (const float*)d_in[3];
    const float* mb = (const float*)d_in[4];
    const float* dw = (const float*)d_in[5];
    const float* db = (const float*)d_in[6];
    float* out = (float*)d_out;

    cudaFuncSetAttribute(offmask_mma_kernel,
                         cudaFuncAttributeMaxDynamicSharedMemorySize, SMEM2);
    cudaFuncSetAttribute(deform_kernel,
                         cudaFuncAttributeMaxDynamicSharedMemorySize, SMEM2);

    prep_b_kernel<<<(Cc * CK + 255) / 256, 256>>>(dw);
    prep_bo_kernel<<<(9 * 64 * 32 + 255) / 256, 256>>>(ow, mw);
    offmask_mma_kernel<<<(Bb * HW) / 128, 256, SMEM2>>>(x, ob, mb);
    deform_kernel<<<(Bb * HW) / 128, 256, SMEM2>>>(x, db, out);
}

// round 10
// speedup vs baseline: 9.7668x; 1.6678x over previous
#include <cuda_runtime.h>
#include <cuda_bf16.h>
#include <cstdint>
#include <math.h>

#define Bb  8
#define Cc  64
#define Hh  128
#define Ww  128
#define HW  (Hh*Ww)
#define K2  9
#define OCT 27
#define CK  (Cc*K2)     // 576

// ---------------------------------------------------------------------------
// helpers
// ---------------------------------------------------------------------------
__device__ __forceinline__ uint32_t smem_to_u32(const void* p) {
    uint32_t a;
    asm("{ .reg .u64 t; cvta.to.shared.u64 t, %1; cvt.u32.u64 %0, t; }"
        : "=r"(a) : "l"(p));
    return a;
}
#define LDSM_X4(r, ad) \
    asm volatile("ldmatrix.sync.aligned.m8n8.x4.shared.b16 {%0,%1,%2,%3}, [%4];" \
        : "=r"((r)[0]), "=r"((r)[1]), "=r"((r)[2]), "=r"((r)[3]) : "r"(ad))
#define LDSM_X4T(r, ad) \
    asm volatile("ldmatrix.sync.aligned.m8n8.x4.trans.shared.b16 {%0,%1,%2,%3}, [%4];" \
        : "=r"((r)[0]), "=r"((r)[1]), "=r"((r)[2]), "=r"((r)[3]) : "r"(ad))
#define STS128(ad, r0, r1, r2, r3) \
    asm volatile("st.shared.v4.b32 [%0], {%1,%2,%3,%4};" \
        :: "r"(ad), "r"(r0), "r"(r1), "r"(r2), "r"(r3) : "memory")
#define MMA_BF16(d, a, b0, b1) \
    asm volatile("mma.sync.aligned.m16n8k16.row.col.f32.bf16.bf16.f32 " \
        "{%0,%1,%2,%3}, {%4,%5,%6,%7}, {%8,%9}, {%0,%1,%2,%3};" \
        : "+f"((d)[0]), "+f"((d)[1]), "+f"((d)[2]), "+f"((d)[3]) \
        : "r"((a)[0]), "r"((a)[1]), "r"((a)[2]), "r"((a)[3]), "r"(b0), "r"(b1))
__device__ __forceinline__ void cp_async16(uint32_t dst, const void* src) {
    asm volatile("cp.async.cg.shared.global [%0], [%1], 16;"
                 :: "r"(dst), "l"(src) : "memory");
}
#define CP_COMMIT() asm volatile("cp.async.commit_group;" ::: "memory")
#define CP_WAIT1()  asm volatile("cp.async.wait_group 1;" ::: "memory")
#define CP_WAIT0()  asm volatile("cp.async.wait_group 0;" ::: "memory")

// ---------------------------------------------------------------------------
// pre-swizzled bf16 B tiles: [9 chunks][64 k-rows x 64 cols], 128B rows, SW128.
__device__ uint4 g_Bh4[9*8192/16];    // deform weights, hi
__device__ uint4 g_Bl4[9*8192/16];    // deform weights, lo
__device__ uint4 g_BOh4[9*8192/16];   // offset+mask weights (cols 0..26), hi
__device__ uint4 g_BOl4[9*8192/16];   // lo

// ---------------------------------------------------------------------------
// Weight prep (deform): dw[o][c][k] -> B[k][row=c][col=o], bf16 hi/lo, swizzled.
__global__ void prep_b_kernel(const float* __restrict__ dw) {
    int i = blockIdx.x * 256 + threadIdx.x;
    if (i >= Cc * CK) return;
    int o = i / CK;
    int r = i - o * CK;
    int c = r / 9;
    int k = r - c * 9;
    float v = dw[i];
    __nv_bfloat16 hi = __float2bfloat16(v);
    __nv_bfloat16 lo = __float2bfloat16(v - __bfloat162float(hi));
    uint32_t off = (uint32_t)c * 128u + (uint32_t)o * 2u;
    uint32_t sw  = off ^ ((off >> 3) & 0x70u);
    ((__nv_bfloat16*)g_Bh4)[k * 4096 + (sw >> 1)] = hi;
    ((__nv_bfloat16*)g_Bl4)[k * 4096 + (sw >> 1)] = lo;
}

// Weight prep (offset+mask): cols 0..17 = ow ch j, 18..26 = mw ch j-18, 27..31 = 0.
__global__ void prep_bo_kernel(const float* __restrict__ ow,
                               const float* __restrict__ mw) {
    int i = blockIdx.x * 256 + threadIdx.x;          // 9*64*32
    if (i >= 9 * 64 * 32) return;
    int k = i >> 11;
    int c = (i >> 5) & 63;
    int j = i & 31;
    float v = 0.f;
    if (j < 18)      v = ow[j * CK + c * 9 + k];
    else if (j < 27) v = mw[(j - 18) * CK + c * 9 + k];
    __nv_bfloat16 hi = __float2bfloat16(v);
    __nv_bfloat16 lo = __float2bfloat16(v - __bfloat162float(hi));
    uint32_t off = (uint32_t)c * 128u + (uint32_t)j * 2u;
    uint32_t sw  = off ^ ((off >> 3) & 0x70u);
    ((__nv_bfloat16*)g_BOh4)[k * 4096 + (sw >> 1)] = hi;
    ((__nv_bfloat16*)g_BOl4)[k * 4096 + (sw >> 1)] = lo;
}

// ---------------------------------------------------------------------------
// smem layout (per CTA, 79360 B -> 2 CTAs/SM):
//   [0, 32768)       B double-buffer: buf*16384, hi @ +0, lo @ +8192
//   [32768, 49152)   A hi (128 rows x 128B, SW128)
//   [49152, 65536)   A lo
//   [65536, 79360)   s_dy/s_dx/s_mk  (128 px x 9 floats each)
#define SM_A_HI 32768
#define SM_A_LO 49152
#define SM_OFF  65536
#define SMEM_F  79360

// prefetch one 16KB (hi+lo) chunk into buffer `buf` via cp.async
__device__ __forceinline__ void prefetch_chunk(uint32_t smem_base, int buf,
                                               const uint4* __restrict__ Bh,
                                               const uint4* __restrict__ Bl,
                                               int ch, int tid) {
    const uint32_t dst = smem_base + (uint32_t)buf * 16384u;
    const uint4* sh = Bh + ch * 512;
    const uint4* sl = Bl + ch * 512;
#pragma unroll
    for (int r = 0; r < 2; r++) {
        int i = tid + r * 256;
        cp_async16(dst + (uint32_t)i * 16u, sh + i);
        cp_async16(dst + 8192u + (uint32_t)i * 16u, sl + i);
    }
    CP_COMMIT();
}

// ---------------------------------------------------------------------------
// Fused offset/mask conv + deformable conv. One CTA = 128 pixels, 256 threads.
// Phase 1: offmask GEMM (N=32, 27 used) -> dy/dx/mask in smem.
// Phase 2: deform GEMM (N=64) with bilinear-sampled modulated A.
// B streamed chunk-by-chunk (cp.async double buffer), bridging both phases.
__global__ __launch_bounds__(256, 2)
void fused_kernel(const float* __restrict__ x,
                  const float* __restrict__ obias,
                  const float* __restrict__ mbias,
                  const float* __restrict__ db,
                  float* __restrict__ out)
{
    extern __shared__ char smd[];
    const uint32_t smem_base = smem_to_u32(smd);
    const int tid = threadIdx.x;

    // sampling-role mapping
    const int set = tid >> 7;        // channel half (32 ch)
    const int p   = tid & 127;       // pixel row within CTA
    const int pixel = blockIdx.x * 128 + p;
    const int b  = pixel >> 14;
    const int hw = pixel & (HW - 1);
    const int h  = hw >> 7;
    const int w  = hw & 127;
    const float* xb = x + (size_t)b * Cc * HW + (size_t)(set * 32) * HW;
    const uint32_t a_row_byte = (uint32_t)p * 128u;
    const uint32_t a_row_sw   = ((uint32_t)(p & 7)) << 4;

    // MMA-role mapping
    const int wid  = tid >> 5;
    const int lane = tid & 31;
    const int m0   = wid * 16;
    const uint32_t lm_arow  = (uint32_t)(m0 + (lane & 15));
    const uint32_t lm_asub  = ((uint32_t)(lane >> 4) & 1u) * 16u;
    const uint32_t lm_asw   = (lm_arow & 7u) << 4;
    const uint32_t lm_abase = lm_arow * 128u;
    const uint32_t lm_bkrow = (uint32_t)(lane & 15);
    const uint32_t lm_bnsub = ((uint32_t)(lane >> 4) & 1u) * 16u;

    float* s_dy = (float*)(smd + SM_OFF);
    float* s_dx = s_dy + 1152;
    float* s_mk = s_dx + 1152;

    // prologue: BO chunk 0 -> buf0
    prefetch_chunk(smem_base, 0, g_BOh4, g_BOl4, 0, tid);

    // ======================= PHASE 1: offset + mask =======================
    {
        float acc[4][4];
#pragma unroll
        for (int n = 0; n < 4; n++)
#pragma unroll
            for (int q = 0; q < 4; q++) acc[n][q] = 0.f;

        for (int ch = 0; ch < 9; ch++) {
            const int hh = h + ch / 3 - 1;
            const int ww = w + ch % 3 - 1;
            const bool ok = ((unsigned)hh < (unsigned)Hh) && ((unsigned)ww < (unsigned)Ww);
            const int ioff = hh * Ww + ww;

            uint32_t hi16[16], lo16[16];
            {
                const float* xc = xb;
#pragma unroll
                for (int i = 0; i < 16; i++) {
                    float s0 = ok ? xc[ioff] : 0.f;  xc += HW;
                    float s1 = ok ? xc[ioff] : 0.f;  xc += HW;
                    __nv_bfloat16 h0b = __float2bfloat16(s0);
                    __nv_bfloat16 h1b = __float2bfloat16(s1);
                    __nv_bfloat162 hp = __nv_bfloat162(h0b, h1b);
                    __nv_bfloat162 lp = __floats2bfloat162_rn(s0 - __bfloat162float(h0b),
                                                              s1 - __bfloat162float(h1b));
                    hi16[i] = *(uint32_t*)&hp;
                    lo16[i] = *(uint32_t*)&lp;
                }
            }

            __syncthreads();   // B1: prior MMAs done -> safe to refill buffers / A
            if (ch < 8) prefetch_chunk(smem_base, (ch + 1) & 1, g_BOh4, g_BOl4, ch + 1, tid);
            else        prefetch_chunk(smem_base, 1, g_Bh4, g_Bl4, 0, tid);  // bridge

#pragma unroll
            for (int u = 0; u < 4; u++) {
                uint32_t col = (((uint32_t)set * 64u) + (uint32_t)u * 16u) ^ a_row_sw;
                STS128(smem_base + SM_A_HI + a_row_byte + col,
                       hi16[u*4+0], hi16[u*4+1], hi16[u*4+2], hi16[u*4+3]);
                STS128(smem_base + SM_A_LO + a_row_byte + col,
                       lo16[u*4+0], lo16[u*4+1], lo16[u*4+2], lo16[u*4+3]);
            }
            CP_WAIT1();        // chunk ch landed (next chunk may be in flight)
            __syncthreads();   // B2: A stores + everyone's cp.async visible

            const uint32_t bh_base = smem_base + (uint32_t)(ch & 1) * 16384u;
            const uint32_t bl_base = bh_base + 8192u;
#pragma unroll
            for (int ks = 0; ks < 4; ks++) {
                uint32_t kcol = (((uint32_t)ks * 32u) + lm_asub) ^ lm_asw;
                uint32_t ah[4], al[4];
                LDSM_X4(ah, smem_base + SM_A_HI + lm_abase + kcol);
                LDSM_X4(al, smem_base + SM_A_LO + lm_abase + kcol);
                const uint32_t brow = (uint32_t)ks * 16u + lm_bkrow;
                const uint32_t bsw  = (brow & 7u) << 4;
                const uint32_t boff = brow * 128u;
                uint32_t bh[4], bl[4];
                uint32_t ncol = lm_bnsub ^ bsw;
                LDSM_X4T(bh, bh_base + boff + ncol);
                LDSM_X4T(bl, bl_base + boff + ncol);
                MMA_BF16(acc[0], ah, bh[0], bh[1]);
                MMA_BF16(acc[0], ah, bl[0], bl[1]);
                MMA_BF16(acc[0], al, bh[0], bh[1]);
                MMA_BF16(acc[1], ah, bh[2], bh[3]);
                MMA_BF16(acc[1], ah, bl[2], bl[3]);
                MMA_BF16(acc[1], al, bh[2], bh[3]);
                uint32_t ncol2 = (32u + lm_bnsub) ^ bsw;
                LDSM_X4T(bh, bh_base + boff + ncol2);
                LDSM_X4T(bl, bl_base + boff + ncol2);
                MMA_BF16(acc[2], ah, bh[0], bh[1]);
                MMA_BF16(acc[2], ah, bl[0], bl[1]);
                MMA_BF16(acc[2], al, bh[0], bh[1]);
                MMA_BF16(acc[3], ah, bh[2], bh[3]);
                MMA_BF16(acc[3], ah, bl[2], bl[3]);
                MMA_BF16(acc[3], al, bh[2], bh[3]);
            }
        }

        // epilogue -> smem dy/dx/mask
        const int r0 = m0 + (lane >> 2);
#pragma unroll
        for (int nt = 0; nt < 4; nt++) {
            const int j0 = nt * 8 + (lane & 3) * 2;
#pragma unroll
            for (int q = 0; q < 4; q++) {
                const int j = j0 + (q & 1);
                if (j >= 27) continue;
                const int P = r0 + ((q >> 1) << 3);
                const float v = acc[nt][q];
                if (j < 18) {
                    float t = v + obias[j];
                    if ((j & 1) == 0) s_dy[P * 9 + (j >> 1)] = t;
                    else              s_dx[P * 9 + (j >> 1)] = t;
                } else {
                    float z = v + mbias[j - 18];
                    s_mk[P * 9 + (j - 18)] = 1.f / (1.f + expf(-z));
                }
            }
        }
    }
    __syncthreads();   // offsets visible to deform sampling

    // ========================= PHASE 2: deform ===========================
    float acc2[8][4];
#pragma unroll
    for (int n = 0; n < 8; n++)
#pragma unroll
        for (int q = 0; q < 4; q++) acc2[n][q] = 0.f;

    for (int ch = 0; ch < 9; ch++) {
        const int k = ch;
        const float m  = s_mk[p * 9 + k];
        const float py = (float)(h + k / 3 - 1) + s_dy[p * 9 + k];
        const float px = (float)(w + k % 3 - 1) + s_dx[p * 9 + k];
        const float yf = floorf(py), xf = floorf(px);
        const int   y0 = (int)yf,  x0 = (int)xf;
        const float ly = py - yf,  lx = px - xf;
        const bool y0v = (unsigned)y0       < (unsigned)Hh;
        const bool y1v = (unsigned)(y0 + 1) < (unsigned)Hh;
        const bool x0v = (unsigned)x0       < (unsigned)Ww;
        const bool x1v = (unsigned)(x0 + 1) < (unsigned)Ww;
        const float w00 = (y0v && x0v) ? (1.f - ly) * (1.f - lx) * m : 0.f;
        const float w01 = (y0v && x1v) ? (1.f - ly) * lx         * m : 0.f;
        const float w10 = (y1v && x0v) ? ly         * (1.f - lx) * m : 0.f;
        const float w11 = (y1v && x1v) ? ly         * lx         * m : 0.f;
        const int cy0 = min(max(y0, 0), Hh - 1), cy1 = min(max(y0 + 1, 0), Hh - 1);
        const int cx0 = min(max(x0, 0), Ww - 1), cx1 = min(max(x0 + 1, 0), Ww - 1);
        const int i00 = cy0 * Ww + cx0, i01 = cy0 * Ww + cx1;
        const int i10 = cy1 * Ww + cx0, i11 = cy1 * Ww + cx1;

        uint32_t hi16[16], lo16[16];
        {
            const float* xc = xb;
#pragma unroll
            for (int i = 0; i < 16; i++) {
                float s0 = w00 * xc[i00] + w01 * xc[i01] + w10 * xc[i10] + w11 * xc[i11];
                xc += HW;
                float s1 = w00 * xc[i00] + w01 * xc[i01] + w10 * xc[i10] + w11 * xc[i11];
                xc += HW;
                __nv_bfloat16 h0b = __float2bfloat16(s0);
                __nv_bfloat16 h1b = __float2bfloat16(s1);
                __nv_bfloat162 hp = __nv_bfloat162(h0b, h1b);
                __nv_bfloat162 lp = __floats2bfloat162_rn(s0 - __bfloat162float(h0b),
                                                          s1 - __bfloat162float(h1b));
                hi16[i] = *(uint32_t*)&hp;
                lo16[i] = *(uint32_t*)&lp;
            }
        }

        __syncthreads();   // B1
        if (ch < 8) prefetch_chunk(smem_base, ch & 1, g_Bh4, g_Bl4, ch + 1, tid);

#pragma unroll
        for (int u = 0; u < 4; u++) {
            uint32_t col = (((uint32_t)set * 64u) + (uint32_t)u * 16u) ^ a_row_sw;
            STS128(smem_base + SM_A_HI + a_row_byte + col,
                   hi16[u*4+0], hi16[u*4+1], hi16[u*4+2], hi16[u*4+3]);
            STS128(smem_base + SM_A_LO + a_row_byte + col,
                   lo16[u*4+0], lo16[u*4+1], lo16[u*4+2], lo16[u*4+3]);
        }
        if (ch < 8) { CP_WAIT1(); } else { CP_WAIT0(); }
        __syncthreads();   // B2

        // deform chunk ch lives in buf (ch+1)&1 (bridge put chunk0 in buf1)
        const uint32_t bh_base = smem_base + (uint32_t)((ch + 1) & 1) * 16384u;
        const uint32_t bl_base = bh_base + 8192u;
#pragma unroll
        for (int ks = 0; ks < 4; ks++) {
            uint32_t kcol = (((uint32_t)ks * 32u) + lm_asub) ^ lm_asw;
            uint32_t ah[4], al[4];
            LDSM_X4(ah, smem_base + SM_A_HI + lm_abase + kcol);
            LDSM_X4(al, smem_base + SM_A_LO + lm_abase + kcol);
            const uint32_t brow = (uint32_t)ks * 16u + lm_bkrow;
            const uint32_t bsw  = (brow & 7u) << 4;
            const uint32_t boff = brow * 128u;
#pragma unroll
            for (int nt2 = 0; nt2 < 4; nt2++) {
                uint32_t ncol = (((uint32_t)nt2 * 32u) + lm_bnsub) ^ bsw;
                uint32_t bh[4], bl[4];
                LDSM_X4T(bh, bh_base + boff + ncol);
                LDSM_X4T(bl, bl_base + boff + ncol);
                MMA_BF16(acc2[2*nt2],     ah, bh[0], bh[1]);
                MMA_BF16(acc2[2*nt2],     ah, bl[0], bl[1]);
                MMA_BF16(acc2[2*nt2],     al, bh[0], bh[1]);
                MMA_BF16(acc2[2*nt2 + 1], ah, bh[2], bh[3]);
                MMA_BF16(acc2[2*nt2 + 1], ah, bl[2], bl[3]);
                MMA_BF16(acc2[2*nt2 + 1], al, bh[2], bh[3]);
            }
        }
    }

    // ---- epilogue: acc2 fragment -> out[b][o][hw] (+bias) ----
    const int pix0 = blockIdx.x * 128;
    const int bB   = pix0 >> 14;
    const int hw0  = (pix0 & (HW - 1)) + m0 + (lane >> 2);
    float* ob = out + (size_t)bB * Cc * HW;
#pragma unroll
    for (int nt = 0; nt < 8; nt++) {
        const int ch0 = nt * 8 + (lane & 3) * 2;
        const float b0 = db[ch0], b1 = db[ch0 + 1];
        ob[(size_t)ch0       * HW + hw0]     = acc2[nt][0] + b0;
        ob[(size_t)(ch0 + 1) * HW + hw0]     = acc2[nt][1] + b1;
        ob[(size_t)ch0       * HW + hw0 + 8] = acc2[nt][2] + b0;
        ob[(size_t)(ch0 + 1) * HW + hw0 + 8] = acc2[nt][3] + b1;
    }
}

// ---------------------------------------------------------------------------
extern "C" void kernel_launch(void* const* d_in, const int* in_sizes, int n_in,
                              void* d_out, int out_size)
{
    const float* x  = (const float*)d_in[0];
    const float* ow = (const float*)d_in[1];
    const float* ob = (const float*)d_in[2];
    const float* mw = (const float*)d_in[3];
    const float* mb = (const float*)d_in[4];
    const float* dw = (const float*)d_in[5];
    const float* db = (const float*)d_in[6];
    float* out = (float*)d_out;

    cudaFuncSetAttribute(fused_kernel,
                         cudaFuncAttributeMaxDynamicSharedMemorySize, SMEM_F);

    prep_b_kernel<<<(Cc * CK + 255) / 256, 256>>>(dw);
    prep_bo_kernel<<<(9 * 64 * 32 + 255) / 256, 256>>>(ow, mw);
    fused_kernel<<<(Bb * HW) / 128, 256, SMEM_F>>>(x, ob, mb, db, out);
}